// round 8
// baseline (speedup 1.0000x reference)
#include <cuda_runtime.h>
#include <cstdint>

constexpr int T = 512, B = 64, F = 32, K = 32;

#define FULL 0xffffffffu
#define VOLI(x) (*(volatile int*)&(x))

__device__ __forceinline__ float ex2f(float x) {
    float y; asm("ex2.approx.f32 %0, %1;" : "=f"(y) : "f"(x)); return y;
}
__device__ __forceinline__ float lg2f(float x) {
    float y; asm("lg2.approx.f32 %0, %1;" : "=f"(y) : "f"(x)); return y;
}

constexpr float L2E  = 1.4426950408889634f;
constexpr float LN2  = 0.6931471805599453f;
constexpr float LN32 = 3.4657359027997265f;

constexpr int NPROD = 8;
constexpr int FR    = 64;   // feats ring depth

// One persistent block per batch b.  Warp roles (hi-wid = hi arbiter priority):
//   wid 0..7 : feats producers  -> global feats + smem ring
//   wid 8,9  : backpointer consumers (trail vit via s_vw watermark)
//   wid 10   : forward chain (linear domain) -> score[b]
//   wid 11   : Viterbi chain -> maxs[1..]
__global__ void __launch_bounds__(384, 1)
crf_fused(const int* __restrict__ words, const int* __restrict__ lens,
          const float* __restrict__ W, const float* __restrict__ trans,
          float* __restrict__ feats, float* __restrict__ maxs,
          float* __restrict__ idxo, float* __restrict__ score)
{
    __shared__ float fring[FR][K];
    __shared__ int   s_prog[NPROD];   // row r done iff s_prog[r%8] >= r
    __shared__ int   s_cons[2];       // fwd/vit consumed-up-to (ring space)
    __shared__ int   s_vw;            // maxs[<=s_vw] globally visible

    int tid  = threadIdx.x;
    int wid  = tid >> 5;
    int lane = tid & 31;
    int b    = blockIdx.x;

    if (tid < NPROD) s_prog[tid] = -1;
    if (tid < 2)     s_cons[tid] = 0;
    if (tid == 0)    s_vw = -1;
    __syncthreads();

    int L = __ldg(&lens[b]);          // uniform within block

    auto wait_prog = [&](int need) {
        volatile int* sp = s_prog;
        for (;;) {
            int m = sp[0];
#pragma unroll
            for (int i = 1; i < NPROD; i++) m = min(m, sp[i]);
            if (m >= need) break;
        }
        __threadfence_block();
    };

    if (wid < NPROD) {
        // ======================= producers =======================
        int p = wid;
        float w0v = __ldg(&W[0]) * 32.f;          // pad-row value (all lanes)
        for (int t = p; t < T; t += NPROD) {
            if (t >= FR) {
                while (min(VOLI(s_cons[0]), VOLI(s_cons[1])) < t - (FR - 16))
                    __nanosleep(40);
            }
            float s;
            if (t < L) {
                int gw = t * B + b;
                int w = __ldg(&words[gw * F + lane]);
                float s0 = 0.f, s1 = 0.f, s2 = 0.f, s3 = 0.f;
#pragma unroll
                for (int f = 0; f < F; f += 4) {
                    int w0 = __shfl_sync(FULL, w, f);
                    int w1 = __shfl_sync(FULL, w, f + 1);
                    int w2 = __shfl_sync(FULL, w, f + 2);
                    int w3 = __shfl_sync(FULL, w, f + 3);
                    s0 += __ldg(&W[w0 + lane]); s1 += __ldg(&W[w1 + lane]);
                    s2 += __ldg(&W[w2 + lane]); s3 += __ldg(&W[w3 + lane]);
                }
                s = (s0 + s1) + (s2 + s3);
            } else {
                s = w0v;      // idx masked to 0 after tag shift -> 32*W[0]
            }
            feats[(t * B + b) * K + lane] = s;
            if (t == 0) {
                maxs[b * K + lane] = s;      // max_s[0] = feats[0]
                idxo[b * K + lane] = 0.f;    // max_s_idx[0] = 0
            }
            fring[t & (FR - 1)][lane] = s;
            __syncwarp();
            __threadfence_block();
            __syncwarp();
            if (lane == 0) VOLI(s_prog[p]) = t;
        }
        __syncwarp();
        if (lane == 0) VOLI(s_prog[p]) = T;

    } else if (wid < 10) {
        // ==================== backpointer warps ====================
        int q = wid - 8;
        float tc[K];
#pragma unroll
        for (int j = 0; j < K; j++) tc[j] = __ldg(&trans[j * K + lane]);

        int Lc = (L < T) ? L : T;
        for (int t = 1 + q; t < Lc; t += 2) {
            while (VOLI(s_vw) < t - 1) __nanosleep(32);
            __threadfence_block();
            float dp = maxs[((t - 1) * B + b) * K + lane];
            float best = __shfl_sync(FULL, dp, 0) + tc[0];
            int   bi   = 0;
#pragma unroll
            for (int j = 1; j < K; j++) {
                float sc = __shfl_sync(FULL, dp, j) + tc[j];
                if (sc > best) { best = sc; bi = j; }   // strict > : first index
            }
            idxo[(t * B + b) * K + lane] = (float)bi;
        }
        if (L < T) {
            while (VOLI(s_vw) < L - 1) __nanosleep(32);
            __threadfence_block();
            float dp = maxs[((L - 1) * B + b) * K + lane];
            float best = __shfl_sync(FULL, dp, 0) + tc[0];
            int   bi   = 0;
#pragma unroll
            for (int j = 1; j < K; j++) {
                float sc = __shfl_sync(FULL, dp, j) + tc[j];
                if (sc > best) { best = sc; bi = j; }
            }
            float v = (float)bi;
            int t0 = L + (((1 + q) - L) & 1);
            if (t0 < 1 + q) t0 = 1 + q;
#pragma unroll 4
            for (int t = t0; t < T; t += 2)
                idxo[(t * B + b) * K + lane] = v;
        }

    } else if (wid == 10) {
        // ==================== forward chain (linear domain) ====================
        float et[K];
#pragma unroll
        for (int j = 0; j < K; j++) et[j] = ex2f(__ldg(&trans[j * K + lane]) * L2E);

        wait_prog(min(15, T - 1));
        float f0 = fring[0][lane];
        float C0 = __shfl_sync(FULL, f0, 0);
        float E    = ex2f((f0 - C0) * L2E);
        float Ctot = C0;

        for (int t = 1; t < L; t++) {
            if ((t & 15) == 0) {
                wait_prog(min(t + 15, T - 1));
                if (lane == 0) VOLI(s_cons[0]) = t - 1;
            }
            float f  = fring[t & (FR - 1)][lane];
            float xf = ex2f(fmaf(f, L2E, -5.f));          // exp(f)/32, off-path

            float s0 = 0.f, s1 = 0.f, s2 = 0.f, s3 = 0.f;
#pragma unroll
            for (int j = 0; j < K; j += 4) {
                s0 = fmaf(__shfl_sync(FULL, E, j),     et[j],     s0);
                s1 = fmaf(__shfl_sync(FULL, E, j + 1), et[j + 1], s1);
                s2 = fmaf(__shfl_sync(FULL, E, j + 2), et[j + 2], s2);
                s3 = fmaf(__shfl_sync(FULL, E, j + 3), et[j + 3], s3);
            }
            E = ((s0 + s1) + (s2 + s3)) * xf;
            Ctot += LN32;
            if ((t & 127) == 0) {                         // renorm (alpha-preserving)
                float rr = __shfl_sync(FULL, E, 0);
                float cc = lg2f(rr);
                E *= ex2f(-cc);
                Ctot += cc * LN2;
            }
        }
        float e = E;
#pragma unroll
        for (int o = 16; o; o >>= 1) e += __shfl_xor_sync(FULL, e, o);
        if (lane == 0) score[b] = Ctot + lg2f(e) * LN2;
        __syncwarp();
        if (lane == 0) VOLI(s_cons[0]) = T + FR;

    } else {
        // ==================== Viterbi chain ====================
        float tc[K];
#pragma unroll
        for (int j = 0; j < K; j++) tc[j] = __ldg(&trans[j * K + lane]);

        wait_prog(min(15, T - 1));
        float delta = fring[0][lane];
        if (lane == 0) VOLI(s_vw) = 0;      // maxs[0] written+fenced by producer 0

        for (int t = 1; t < L; t++) {
            if ((t & 15) == 0) {
                wait_prog(min(t + 15, T - 1));
                __syncwarp();
                __threadfence_block();
                if (lane == 0) { VOLI(s_vw) = t - 1; VOLI(s_cons[1]) = t - 1; }
                __syncwarp();
            }
            float f = fring[t & (FR - 1)][lane];

            const float NEG_INF = __int_as_float(0xff800000);
            float m0 = NEG_INF, m1 = NEG_INF, m2 = NEG_INF, m3 = NEG_INF;
#pragma unroll
            for (int j = 0; j < K; j += 4) {
                m0 = fmaxf(m0, __shfl_sync(FULL, delta, j)     + tc[j]);
                m1 = fmaxf(m1, __shfl_sync(FULL, delta, j + 1) + tc[j + 1]);
                m2 = fmaxf(m2, __shfl_sync(FULL, delta, j + 2) + tc[j + 2]);
                m3 = fmaxf(m3, __shfl_sync(FULL, delta, j + 3) + tc[j + 3]);
            }
            delta = fmaxf(fmaxf(m0, m1), fmaxf(m2, m3)) + f;
            maxs[(t * B + b) * K + lane] = delta;
        }
        // frozen tail
#pragma unroll 4
        for (int t = L; t < T; t++)
            maxs[(t * B + b) * K + lane] = delta;
        __syncwarp();
        __threadfence_block();
        __syncwarp();
        if (lane == 0) { VOLI(s_vw) = T; VOLI(s_cons[1]) = T + FR; }
    }
}

// ---------------------------------------------------------------------------
extern "C" void kernel_launch(void* const* d_in, const int* in_sizes, int n_in,
                              void* d_out, int out_size) {
    const int*   words = (const int*)d_in[0];     // [T,B,F] int32
    const int*   lens  = (const int*)d_in[1];     // [B] int32
    const float* W     = (const float*)d_in[2];   // [1e6] f32
    const float* trans = (const float*)d_in[3];   // [K,K] f32
    float* out   = (float*)d_out;
    float* score = out;
    float* maxs  = out + 64;
    float* idxo  = out + 64 + T * B * K;
    float* feats = out + 64 + 2 * T * B * K;

    crf_fused<<<B, 384>>>(words, lens, W, trans, feats, maxs, idxo, score);
}